// round 10
// baseline (speedup 1.0000x reference)
#include <cuda_runtime.h>
#include <math_constants.h>

#define NPTS 4096
#define WARPS_PER_BLOCK 28
#define NTHREADS 896
#define NBLOCKS 147                           // 147*28 = 4116 >= 4096, 1 block/SM
#define FULL 0xffffffffu

#define GDIM 64
#define GCELLS (GDIM * GDIM)
#define BHALF 5.0f
#define CW 0.15625f                           // 10/64, exact in fp32
#define INVW 6.4f

// dynamic smem: ssx[4096] ssy[4096] sidx[4096] cnt[4096] st[4097] wtot[32]
#define SMEM_BYTES ((NPTS * 3 + GCELLS + (GCELLS + 1) + 32) * 4)

__device__ __forceinline__ bool pless(float da, int ia, float db, int ib) {
    return (da < db) || (da == db && ia < ib);
}
#define CAS(dx, ix, dy, iy)                                  \
    do { if (!pless(dx, ix, dy, iy)) {                       \
        float _t = dx; dx = dy; dy = _t;                     \
        int _u = ix; ix = iy; iy = _u; } } while (0)
#define CASV(a, b) do { float _lo = fminf(a, b), _hi = fmaxf(a, b); a = _lo; b = _hi; } while (0)

__device__ __forceinline__ int cellof(float v) {
    int c = (int)floorf((v + BHALF) * INVW);
    return min(max(c, 0), GDIM - 1);
}

extern __shared__ unsigned smem_raw[];

__global__ void __launch_bounds__(NTHREADS)
nn_tag_pool_kernel(const float2* __restrict__ obs1,
                   const float2* __restrict__ obs2,
                   const float*  __restrict__ W,
                   const float*  __restrict__ bias,
                   float* __restrict__ out)
{
    float*    ssx  = (float*)smem_raw;
    float*    ssy  = ssx + NPTS;
    int*      sidx = (int*)(ssy + NPTS);
    unsigned* cnt  = (unsigned*)(sidx + NPTS);
    unsigned* st   = cnt + GCELLS;            // GCELLS+1 entries
    unsigned* wtot = st + GCELLS + 1;         // 32 entries

    const int tid  = threadIdx.x;
    const int warp = tid >> 5;
    const int lane = tid & 31;

    // ---------------- build: bin the 4096 points into cell-sorted smem -------
    for (int c = tid; c < GCELLS; c += NTHREADS) cnt[c] = 0u;
    __syncthreads();

    for (int j = tid; j < NPTS; j += NTHREADS) {
        float2 p = obs2[j];
        atomicAdd(&cnt[cellof(p.y) * GDIM + cellof(p.x)], 1u);
    }
    __syncthreads();

    // block exclusive scan over 4096 counts (5 cells per thread)
    unsigned loc[5];
    unsigned s = 0;
    const int c0 = tid * 5;
    #pragma unroll
    for (int u = 0; u < 5; ++u) {
        int c = c0 + u;
        loc[u] = (c < GCELLS) ? cnt[c] : 0u;
        s += loc[u];
    }
    unsigned inc = s;
    #pragma unroll
    for (int off = 1; off < 32; off <<= 1) {
        unsigned v = __shfl_up_sync(FULL, inc, off);
        if (lane >= off) inc += v;
    }
    if (lane == 31) wtot[warp] = inc;
    __syncthreads();
    if (warp == 0) {
        unsigned v = (lane < WARPS_PER_BLOCK) ? wtot[lane] : 0u;
        #pragma unroll
        for (int off = 1; off < 32; off <<= 1) {
            unsigned t = __shfl_up_sync(FULL, v, off);
            if (lane >= off) v += t;
        }
        if (lane < WARPS_PER_BLOCK) wtot[lane] = v;
    }
    __syncthreads();
    unsigned run = (warp ? wtot[warp - 1] : 0u) + (inc - s);
    #pragma unroll
    for (int u = 0; u < 5; ++u) {
        int c = c0 + u;
        if (c < GCELLS) { st[c] = run; cnt[c] = run; run += loc[u]; }
    }
    if (tid == 0) st[GCELLS] = NPTS;
    __syncthreads();

    for (int j = tid; j < NPTS; j += NTHREADS) {
        float2 p = obs2[j];
        int c = cellof(p.y) * GDIM + cellof(p.x);
        unsigned pos = atomicAdd(&cnt[c], 1u);
        ssx[pos] = p.x; ssy[pos] = p.y; sidx[pos] = j;
    }
    __syncthreads();

    // ---------------- query: one warp per row, expanding square search -------
    const int i = blockIdx.x * WARPS_PER_BLOCK + warp;
    if (i >= NPTS) return;                     // no further __syncthreads below

    const float2 qv = obs2[i];
    const float qx = qv.x, qy = qv.y;
    const int cx = cellof(qx), cy = cellof(qy);

    float d0 = CUDART_INF_F, d1 = CUDART_INF_F, d2 = CUDART_INF_F, d3 = CUDART_INF_F;
    int   i0 = 0x7fffffff,  i1 = 0x7fffffff,  i2 = 0x7fffffff,  i3 = 0x7fffffff;

    // per-lane private pless-insert over a contiguous candidate span
    auto span = [&](int r, int ca, int cb) {
        unsigned p0 = st[r * GDIM + ca];
        unsigned p1 = st[r * GDIM + cb + 1];
        for (unsigned base = p0; base < p1; base += 32) {
            unsigned p = base + lane;
            if (p < p1) {
                float x = ssx[p], y = ssy[p];
                int   j = sidx[p];
                float ddx = x - qx, ddy = y - qy;
                float dv = fmaf(ddx, ddx, fmaf(ddy, ddy, 1.0f));   // exact form
                if (j != i && pless(dv, j, d3, i3)) {
                    d3 = dv; i3 = j;
                    if (pless(d3,i3,d2,i2)) { float t=d3; d3=d2; d2=t; int u=i3; i3=i2; i2=u; }
                    if (pless(d2,i2,d1,i1)) { float t=d2; d2=d1; d1=t; int u=i2; i2=i1; i1=u; }
                    if (pless(d1,i1,d0,i0)) { float t=d1; d1=d0; d0=t; int u=i1; i1=i0; i0=u; }
                }
            }
        }
    };

    for (int k = 0; k < GDIM; ++k) {
        const int rlo = cy - k, rhi = cy + k;
        const int cl = max(cx - k, 0), cr = min(cx + k, GDIM - 1);
        if (rlo >= 0) span(rlo, cl, cr);                  // top row (k=0: own cell row)
        if (k > 0 && rhi < GDIM) span(rhi, cl, cr);       // bottom row
        if (k > 0) {                                      // side columns, middle rows
            const int rl = max(rlo + 1, 0), rh = min(rhi - 1, GDIM - 1);
            const bool lv = (cx - k) >= 0, rv = (cx + k) < GDIM;
            for (int r = rl; r <= rh; ++r) {
                if (lv) span(r, cx - k, cx - k);
                if (rv) span(r, cx + k, cx + k);
            }
        }
        if (k == 0) continue;                  // bound 1 > d4 never holds at k=0

        // warp-wide exact 4th-smallest distance (values-only butterfly merge)
        float e0 = d0, e1 = d1, e2 = d2, e3 = d3;
        #pragma unroll
        for (int off = 16; off >= 1; off >>= 1) {
            float f0 = __shfl_xor_sync(FULL, e0, off);
            float f1 = __shfl_xor_sync(FULL, e1, off);
            float f2 = __shfl_xor_sync(FULL, e2, off);
            float f3 = __shfl_xor_sync(FULL, e3, off);
            float m0 = fminf(e0, f3);
            float m1 = fminf(e1, f2);
            float m2 = fminf(e2, f1);
            float m3 = fminf(e3, f0);
            CASV(m0, m2); CASV(m1, m3); CASV(m0, m1); CASV(m2, m3);
            e0 = m0; e1 = m1; e2 = m2; e3 = m3;
        }
        // unseen points are in cells at Chebyshev >= k+1  =>  dist >= k*W
        float kw = (float)k * CW * 0.999f;     // conservative slack for fp rounding
        if (fmaf(kw, kw, 1.0f) > e3) break;    // e3 finite implies >= 4 found
    }

    // final indexed butterfly merge: 32 private sorted-4 -> warp-uniform top-4
    #pragma unroll
    for (int off = 16; off >= 1; off >>= 1) {
        float f0 = __shfl_xor_sync(FULL, d0, off);
        float f1 = __shfl_xor_sync(FULL, d1, off);
        float f2 = __shfl_xor_sync(FULL, d2, off);
        float f3 = __shfl_xor_sync(FULL, d3, off);
        int   g0 = __shfl_xor_sync(FULL, i0, off);
        int   g1 = __shfl_xor_sync(FULL, i1, off);
        int   g2 = __shfl_xor_sync(FULL, i2, off);
        int   g3 = __shfl_xor_sync(FULL, i3, off);

        float m0, m1, m2, m3; int n0, n1, n2, n3;
        if (pless(d0, i0, f3, g3)) { m0 = d0; n0 = i0; } else { m0 = f3; n0 = g3; }
        if (pless(d1, i1, f2, g2)) { m1 = d1; n1 = i1; } else { m1 = f2; n1 = g2; }
        if (pless(d2, i2, f1, g1)) { m2 = d2; n2 = i2; } else { m2 = f1; n2 = g1; }
        if (pless(d3, i3, f0, g0)) { m3 = d3; n3 = i3; } else { m3 = f0; n3 = g0; }

        CAS(m0, n0, m2, n2); CAS(m1, n1, m3, n3);
        CAS(m0, n0, m1, n1); CAS(m2, n2, m3, n3);

        d0 = m0; d1 = m1; d2 = m2; d3 = m3;
        i0 = n0; i1 = n1; i2 = n2; i3 = n3;
    }

    // ---------------- epilogue: lane kk*8+o -> channel o of neighbor kk ------
    const int o = lane & 7;
    const float w0 = W[o * 6 + 0];
    const float w1 = W[o * 6 + 1];
    const float w3 = W[o * 6 + 3];
    const float w4 = W[o * 6 + 4];
    const float cb = W[o * 6 + 2] + W[o * 6 + 5] + bias[o];

    const int kk = lane >> 3;
    const int j = (kk == 0) ? i0 : (kk == 1) ? i1 : (kk == 2) ? i2 : i3;

    const float2 pj  = obs2[j];
    const float2 a1j = obs1[j];
    const float2 a1i = obs1[i];

    const float px = pj.x - qx;
    const float py = pj.y - qy;
    const float vx = (pj.x - a1j.x) - (qx - a1i.x);   // vel[j] - vel[i]
    const float vy = (pj.y - a1j.y) - (qy - a1i.y);

    float r = fmaf(px, w0, fmaf(py, w1, fmaf(vx, w3, fmaf(vy, w4, cb))));
    out[i * 32 + lane] = fmaxf(r, 0.0f);
}

extern "C" void kernel_launch(void* const* d_in, const int* in_sizes, int n_in,
                              void* d_out, int out_size) {
    const float2* obs1 = (const float2*)d_in[0];
    const float2* obs2 = (const float2*)d_in[1];
    const float*  Wp   = (const float*)d_in[2];
    const float*  bias = (const float*)d_in[3];
    float* out = (float*)d_out;

    cudaFuncSetAttribute(nn_tag_pool_kernel,
                         cudaFuncAttributeMaxDynamicSharedMemorySize, SMEM_BYTES);
    nn_tag_pool_kernel<<<NBLOCKS, NTHREADS, SMEM_BYTES>>>(obs1, obs2, Wp, bias, out);
}